// round 1
// baseline (speedup 1.0000x reference)
#include <cuda_runtime.h>
#include <math.h>

#define FULLM 0xffffffffu

__device__ __forceinline__ float silu_f(float v) {
    return __fdividef(v, 1.f + __expf(-v));
}

__global__ void __launch_bounds__(256)
jastrow_kernel(
    const float* __restrict__ x,
    const float* __restrict__ W_node, const float* __restrict__ b_node,
    const float* __restrict__ We1,    const float* __restrict__ be1,
    const float* __restrict__ We2,    const float* __restrict__ be2,
    const float* __restrict__ Wv2e,   const float* __restrict__ We2v,
    const float* __restrict__ Wu1,    const float* __restrict__ bu1,
    const float* __restrict__ Wu2,    const float* __restrict__ bu2,
    const float* __restrict__ Wn1,    const float* __restrict__ bn1,
    const float* __restrict__ Wn2,    const float* __restrict__ bn2,
    const float* __restrict__ Wf1,    const float* __restrict__ bf1,
    const float* __restrict__ Wf2,    const float* __restrict__ bf2,
    const float* __restrict__ Wf3,    const float* __restrict__ bf3,
    float* __restrict__ out)
{
    // ---- shared memory (total ~48.5 KB, fits static 48KB... counted: 12181 floats) ----
    __shared__ float sWe1[160], sbe1[32];
    __shared__ float sWe2[1024], sbe2[32];      // reused as Wn2^T in phase C
    __shared__ float sWu1[3072], sbu1[32];      // reused as Wn1^T in phase C
    __shared__ float sWu2[1024], sbu2[32];
    __shared__ float sWe2v[1024];
    __shared__ float sWv2e[1024];
    __shared__ float sx[96];
    __shared__ float s_hv[1024];
    __shared__ float s_pm[1024];                // p, then m_v
    __shared__ float s_A[1024];                 // Wu1[:,32:64]·p[i], then tmp in phase C
    __shared__ float s_B[1024];                 // Wu1[:,64:96]·p[j], then h_v_new
    __shared__ float s_ps[256];
    __shared__ float s_sc[17];                  // s1[8], cusp[8], cuspTot
    __shared__ float s_fin[130];
    __shared__ float s_f1[64], s_f2[64];

    const int tid = threadIdx.x;
    const int b   = blockIdx.x;
    const float* xb = x + b * 96;

    // ---- stage inputs / weights (transposed to [k][m] for conflict-free lane reads) ----
    for (int idx = tid; idx < 96; idx += 256) sx[idx] = xb[idx];
    for (int idx = tid; idx < 160; idx += 256) {
        int m = idx / 5, k = idx % 5;
        sWe1[k * 32 + m] = We1[idx];
    }
    for (int idx = tid; idx < 1024; idx += 256) {
        int r = idx >> 5, c = idx & 31;
        sWe2[c * 32 + r]  = We2[idx];    // We2[m][k]  -> [k][m]
        sWu2[c * 32 + r]  = Wu2[idx];    // Wu2[m][k]  -> [k][m]
        sWe2v[c * 32 + r] = We2v[idx];   // We2v[h][m] -> [m][h]
        sWv2e[c * 32 + r] = Wv2e[idx];   // Wv2e[m][h] -> [h][m]
    }
    for (int idx = tid; idx < 3072; idx += 256) {
        int m = idx / 96, c = idx % 96;
        sWu1[c * 32 + m] = Wu1[idx];     // Wu1[m][c]  -> [c][m]
    }
    if (tid < 32) {
        sbe1[tid] = be1[tid]; sbe2[tid] = be2[tid];
        sbu1[tid] = bu1[tid]; sbu2[tid] = bu2[tid];
    }
    __syncthreads();

    // ---- h_v[n][h] = [x, spin] @ W_node^T + b_node ----
    for (int idx = tid; idx < 1024; idx += 256) {
        int n = idx >> 5, h = idx & 31;
        float sf = (n >= 16) ? 1.f : 0.f;
        s_hv[idx] = b_node[h]
                  + sx[n*3+0] * W_node[h*4+0]
                  + sx[n*3+1] * W_node[h*4+1]
                  + sx[n*3+2] * W_node[h*4+2]
                  + sf        * W_node[h*4+3];
    }
    __syncthreads();

    // ---- p = h_v @ Wv2e^T ----
    for (int idx = tid; idx < 1024; idx += 256) {
        int n = idx >> 5, m = idx & 31;
        float acc = 0.f;
        #pragma unroll
        for (int h = 0; h < 32; h++) acc += s_hv[n*32 + h] * sWv2e[h*32 + m];
        s_pm[idx] = acc;
    }
    __syncthreads();

    // ---- hoist: A[n][m] = Wu1[m, 32:64]·p[n],  B[n][m] = Wu1[m, 64:96]·p[n] ----
    for (int idx = tid; idx < 1024; idx += 256) {
        int n = idx >> 5, m = idx & 31;
        float a = 0.f, bb = 0.f;
        #pragma unroll
        for (int k = 0; k < 32; k++) {
            float pv = s_pm[n*32 + k];
            a  += sWu1[(32 + k)*32 + m] * pv;
            bb += sWu1[(64 + k)*32 + m] * pv;
        }
        s_A[idx] = a;
        s_B[idx] = bb;
    }
    __syncthreads();

    // ---- edge loop: warp w owns rows i = w, w+8, w+16, w+24; lane = channel m ----
    const int w = tid >> 5, m = tid & 31;
    const float we1_0 = sWe1[m],      we1_1 = sWe1[32 + m], we1_2 = sWe1[64 + m];
    const float we1_3 = sWe1[96 + m], we1_4 = sWe1[128 + m];
    const float be1r = sbe1[m], be2r = sbe2[m], bu1r = sbu1[m], bu2r = sbu2[m];

    float s1_acc = 0.f, cusp_acc = 0.f, ps_acc = 0.f;

    for (int i = w; i < 32; i += 8) {
        const float xi0 = sx[i*3+0], xi1 = sx[i*3+1], xi2 = sx[i*3+2];
        const float aim = s_A[i*32 + m] + bu1r;
        float msg_acc = 0.f;

        for (int j0 = 0; j0 < 32; j0 += 2) {
            const int j1 = j0 + 1;
            float ra0 = xi0 - sx[j0*3+0], ra1 = xi1 - sx[j0*3+1], ra2 = xi2 - sx[j0*3+2];
            float rb0 = xi0 - sx[j1*3+0], rb1 = xi1 - sx[j1*3+1], rb2 = xi2 - sx[j1*3+2];
            float r2a = ra0*ra0 + ra1*ra1 + ra2*ra2;
            float r2b = rb0*rb0 + rb1*rb1 + rb2*rb2;
            float da = sqrtf(r2a + 1e-12f), db = sqrtf(r2b + 1e-12f);

            float t1a = silu_f(be1r + we1_0*ra0 + we1_1*ra1 + we1_2*ra2 + we1_3*da + we1_4*r2a);
            float t1b = silu_f(be1r + we1_0*rb0 + we1_1*rb1 + we1_2*rb2 + we1_3*db + we1_4*r2b);

            float hea = be2r, heb = be2r;
            #pragma unroll
            for (int k = 0; k < 32; k++) {
                float wv = sWe2[k*32 + m];
                hea += wv * __shfl_sync(FULLM, t1a, k);
                heb += wv * __shfl_sync(FULLM, t1b, k);
            }

            float t2a = aim + s_B[j0*32 + m];
            float t2b = aim + s_B[j1*32 + m];
            #pragma unroll
            for (int k = 0; k < 32; k++) {
                float wv = sWu1[k*32 + m];
                t2a += wv * __shfl_sync(FULLM, hea, k);
                t2b += wv * __shfl_sync(FULLM, heb, k);
            }
            t2a = silu_f(t2a); t2b = silu_f(t2b);

            float hna = bu2r, hnb = bu2r;
            #pragma unroll
            for (int k = 0; k < 32; k++) {
                float wv = sWu2[k*32 + m];
                hna += wv * __shfl_sync(FULLM, t2a, k);
                hnb += wv * __shfl_sync(FULLM, t2b, k);
            }

            float mga = 0.f, mgb = 0.f;
            #pragma unroll
            for (int k = 0; k < 32; k++) {
                float wv = sWe2v[k*32 + m];
                mga += wv * __shfl_sync(FULLM, hna, k);
                mgb += wv * __shfl_sync(FULLM, hnb, k);
            }

            if (j0 != i) msg_acc += mga;
            if (j1 != i) msg_acc += mgb;
            if (j0 > i) {
                ps_acc += hea + hna;
                s1_acc += log1pf((r2a + 1e-8f) * 25.f);
                float rc = sqrtf(r2a + 1e-30f);
                float gamma = ((i < 16) == (j0 < 16)) ? 0.25f : 0.5f;
                cusp_acc += gamma * rc * expf(-rc);
            }
            if (j1 > i) {
                ps_acc += heb + hnb;
                s1_acc += log1pf((r2b + 1e-8f) * 25.f);
                float rc = sqrtf(r2b + 1e-30f);
                float gamma = ((i < 16) == (j1 < 16)) ? 0.25f : 0.5f;
                cusp_acc += gamma * rc * expf(-rc);
            }
        }
        s_pm[i*32 + m] = msg_acc;   // m_v row i (p is dead now)
    }
    s_ps[w*32 + m] = ps_acc;
    if (m == 0) { s_sc[w] = s1_acc; s_sc[8 + w] = cusp_acc; }
    __syncthreads();

    // ---- phase C: node update MLP (reuse sWu1/sWe2 for Wn1^T / Wn2^T) ----
    for (int idx = tid; idx < 2048; idx += 256) {
        int h = idx >> 6, k = idx & 63;
        sWu1[k*32 + h] = Wn1[idx];
    }
    for (int idx = tid; idx < 1024; idx += 256) {
        int h = idx >> 5, k = idx & 31;
        sWe2[k*32 + h] = Wn2[idx];
    }
    if (tid < 32) { sbe1[tid] = bn1[tid]; sbe2[tid] = bn2[tid]; }
    __syncthreads();

    for (int idx = tid; idx < 1024; idx += 256) {
        int n = idx >> 5, h = idx & 31;
        float acc = sbe1[h];
        #pragma unroll
        for (int k = 0; k < 32; k++) acc += sWu1[k*32 + h] * s_hv[n*32 + k];
        #pragma unroll
        for (int k = 0; k < 32; k++) acc += sWu1[(32 + k)*32 + h] * s_pm[n*32 + k];
        s_A[idx] = silu_f(acc);
    }
    __syncthreads();
    for (int idx = tid; idx < 1024; idx += 256) {
        int n = idx >> 5, h = idx & 31;
        float acc = sbe2[h];
        #pragma unroll
        for (int k = 0; k < 32; k++) acc += sWe2[k*32 + h] * s_A[n*32 + k];
        s_B[idx] = s_hv[idx] + acc;    // updated h_v
    }
    __syncthreads();

    // ---- assemble f_in (130) ----
    if (tid < 32) {
        float acc = 0.f;
        for (int n = 0; n < 32; n++) acc += s_B[n*32 + tid];
        s_fin[tid]      = acc;
        s_fin[32 + tid] = acc * (1.f / 32.f);
        float ps = 0.f;
        for (int ww = 0; ww < 8; ww++) ps += s_ps[ww*32 + tid];
        s_fin[64 + tid] = ps;
        s_fin[96 + tid] = ps * (1.f / 496.f);
    }
    if (tid == 0) {
        float r2m = 0.f;
        for (int t = 0; t < 96; t++) r2m += sx[t] * sx[t];
        s_fin[128] = r2m * (1.f / 96.f);
        float s1 = 0.f, cu = 0.f;
        for (int ww = 0; ww < 8; ww++) { s1 += s_sc[ww]; cu += s_sc[8 + ww]; }
        s_fin[129] = s1 * (1.f / 496.f);
        s_sc[16] = cu;
    }
    __syncthreads();

    // ---- final MLP 130 -> 64 -> 64 -> 1 (coalesced row-wise warp reductions) ----
    for (int o = w; o < 64; o += 8) {
        float acc = 0.f;
        for (int k = m; k < 130; k += 32) acc += Wf1[o*130 + k] * s_fin[k];
        #pragma unroll
        for (int off = 16; off > 0; off >>= 1) acc += __shfl_down_sync(FULLM, acc, off);
        if (m == 0) s_f1[o] = silu_f(acc + bf1[o]);
    }
    __syncthreads();
    for (int o = w; o < 64; o += 8) {
        float acc = Wf2[o*64 + m] * s_f1[m] + Wf2[o*64 + 32 + m] * s_f1[32 + m];
        #pragma unroll
        for (int off = 16; off > 0; off >>= 1) acc += __shfl_down_sync(FULLM, acc, off);
        if (m == 0) s_f2[o] = silu_f(acc + bf2[o]);
    }
    __syncthreads();
    if (w == 0) {
        float acc = Wf3[m] * s_f2[m] + Wf3[32 + m] * s_f2[32 + m];
        #pragma unroll
        for (int off = 16; off > 0; off >>= 1) acc += __shfl_down_sync(FULLM, acc, off);
        if (m == 0) out[b] = acc + bf3[0] + s_sc[16];
    }
}

extern "C" void kernel_launch(void* const* d_in, const int* in_sizes, int n_in,
                              void* d_out, int out_size) {
    const float* x      = (const float*)d_in[0];
    const float* W_node = (const float*)d_in[1];
    const float* b_node = (const float*)d_in[2];
    const float* We1    = (const float*)d_in[3];
    const float* be1    = (const float*)d_in[4];
    const float* We2    = (const float*)d_in[5];
    const float* be2    = (const float*)d_in[6];
    const float* Wv2e   = (const float*)d_in[7];
    const float* We2v   = (const float*)d_in[8];
    const float* Wu1    = (const float*)d_in[9];
    const float* bu1    = (const float*)d_in[10];
    const float* Wu2    = (const float*)d_in[11];
    const float* bu2    = (const float*)d_in[12];
    const float* Wn1    = (const float*)d_in[13];
    const float* bn1    = (const float*)d_in[14];
    const float* Wn2    = (const float*)d_in[15];
    const float* bn2    = (const float*)d_in[16];
    const float* Wf1    = (const float*)d_in[17];
    const float* bf1    = (const float*)d_in[18];
    const float* Wf2    = (const float*)d_in[19];
    const float* bf2    = (const float*)d_in[20];
    const float* Wf3    = (const float*)d_in[21];
    const float* bf3    = (const float*)d_in[22];

    int B = in_sizes[0] / 96;   // B * N * D  with N=32, D=3
    jastrow_kernel<<<B, 256>>>(x, W_node, b_node, We1, be1, We2, be2,
                               Wv2e, We2v, Wu1, bu1, Wu2, bu2,
                               Wn1, bn1, Wn2, bn2,
                               Wf1, bf1, Wf2, bf2, Wf3, bf3,
                               (float*)d_out);
}

// round 4
// speedup vs baseline: 2.2724x; 2.2724x over previous
#include <cuda_runtime.h>
#include <math.h>

#define FULLM 0xffffffffu

__device__ __forceinline__ float silu_f(float v) {
    return __fdividef(v, 1.f + __expf(-v));
}

// ---- f32x2 packed helpers (Blackwell) ----
__device__ __forceinline__ unsigned long long pk2(float lo, float hi) {
    unsigned long long r;
    asm("mov.b64 %0,{%1,%2};" : "=l"(r) : "f"(lo), "f"(hi));
    return r;
}
__device__ __forceinline__ void upk2(unsigned long long v, float& lo, float& hi) {
    asm("mov.b64 {%0,%1},%2;" : "=f"(lo), "=f"(hi) : "l"(v));
}
__device__ __forceinline__ unsigned long long f2fma(unsigned long long a, unsigned long long b,
                                                    unsigned long long c) {
    unsigned long long r;
    asm("fma.rn.f32x2 %0,%1,%2,%3;" : "=l"(r) : "l"(a), "l"(b), "l"(c));
    return r;
}
__device__ __forceinline__ unsigned long long f2add(unsigned long long a, unsigned long long b) {
    unsigned long long r;
    asm("add.rn.f32x2 %0,%1,%2;" : "=l"(r) : "l"(a), "l"(b));
    return r;
}

// one weight row (32 channels packed as 16 ull = 8 ull2) times scalar-dup td
__device__ __forceinline__ void mac_row(const float* __restrict__ Wrow, unsigned long long td,
                                        unsigned long long acc[16]) {
    const ulonglong2* r = reinterpret_cast<const ulonglong2*>(Wrow);
    #pragma unroll
    for (int q = 0; q < 8; q++) {
        ulonglong2 w = r[q];                 // uniform LDS.128 (broadcast)
        acc[2*q]   = f2fma(w.x, td, acc[2*q]);
        acc[2*q+1] = f2fma(w.y, td, acc[2*q+1]);
    }
}

// acc[m-pair] += W[k][m] * vin[k]  over k=0..31 (W layout: [k*32+m], pairs contiguous)
__device__ __forceinline__ void matvec32(const float* __restrict__ W, const float* __restrict__ vin,
                                         unsigned long long acc[16]) {
    #pragma unroll
    for (int k = 0; k < 32; k++) mac_row(W + k * 32, pk2(vin[k], vin[k]), acc);
}

// column-sum of a (lane x 32ch) register matrix; returns value for channel == lane
__device__ __forceinline__ float tree_reduce(const unsigned long long v[16], int lane) {
    unsigned long long a[8];
    const bool b4 = (lane & 16) != 0;
    #pragma unroll
    for (int q = 0; q < 8; q++) {
        unsigned long long send = b4 ? v[q] : v[q + 8];
        unsigned long long keep = b4 ? v[q + 8] : v[q];
        a[q] = f2add(keep, __shfl_xor_sync(FULLM, send, 16));
    }
    unsigned long long b[4];
    const bool b3 = (lane & 8) != 0;
    #pragma unroll
    for (int q = 0; q < 4; q++) {
        unsigned long long send = b3 ? a[q] : a[q + 4];
        unsigned long long keep = b3 ? a[q + 4] : a[q];
        b[q] = f2add(keep, __shfl_xor_sync(FULLM, send, 8));
    }
    unsigned long long c[2];
    const bool b2 = (lane & 4) != 0;
    #pragma unroll
    for (int q = 0; q < 2; q++) {
        unsigned long long send = b2 ? b[q] : b[q + 2];
        unsigned long long keep = b2 ? b[q + 2] : b[q];
        c[q] = f2add(keep, __shfl_xor_sync(FULLM, send, 4));
    }
    const bool b1 = (lane & 2) != 0;
    unsigned long long s1v = b1 ? c[0] : c[1];
    unsigned long long k1v = b1 ? c[1] : c[0];
    unsigned long long e = f2add(k1v, __shfl_xor_sync(FULLM, s1v, 2));
    float lo, hi;
    upk2(e, lo, hi);
    const bool b0 = (lane & 1) != 0;
    float snd = b0 ? lo : hi;
    float kp  = b0 ? hi : lo;
    return kp + __shfl_xor_sync(FULLM, snd, 1);
}

__global__ void __launch_bounds__(128, 3)
jastrow_kernel(
    const float* __restrict__ x,
    const float* __restrict__ W_node, const float* __restrict__ b_node,
    const float* __restrict__ We1,    const float* __restrict__ be1,
    const float* __restrict__ We2,    const float* __restrict__ be2,
    const float* __restrict__ Wv2e,   const float* __restrict__ We2v,
    const float* __restrict__ Wu1,    const float* __restrict__ bu1,
    const float* __restrict__ Wu2,    const float* __restrict__ bu2,
    const float* __restrict__ Wn1,    const float* __restrict__ bn1,
    const float* __restrict__ Wn2,    const float* __restrict__ bn2,
    const float* __restrict__ Wf1,    const float* __restrict__ bf1,
    const float* __restrict__ Wf2,    const float* __restrict__ bf2,
    const float* __restrict__ Wf3,    const float* __restrict__ bf3,
    float* __restrict__ out)
{
    // region-reused shared memory (~36 KB)
    __shared__ __align__(16) float R1[2048];   // Wu1T[32:96] -> [We2T | Wu1aT] -> Wn1T
    __shared__ __align__(16) float R2[1024];   // Wv2eT -> A_packed -> phaseC tmp
    __shared__ __align__(16) float R3[1024];   // B_packed -> h_v_new
    __shared__ __align__(16) float R4[1024];   // Wu2T -> Wn2T
    __shared__ __align__(16) float R5[1024];   // We2vT
    __shared__ __align__(16) float sWe1[160];
    __shared__ __align__(16) float sbe1[32], sbe2[32], sbu2[32];
    __shared__ __align__(16) float s_hv[1024];
    __shared__ __align__(16) float s_pm[1024]; // p, then m_v
    __shared__ float sx[96];
    __shared__ float s_ps[128];
    __shared__ float s_sc[12];
    __shared__ float s_fin[132];
    __shared__ float s_f1[64], s_f2[64];

    const int tid  = threadIdx.x;
    const int w    = tid >> 5;
    const int lane = tid & 31;
    const int b    = blockIdx.x;
    const float* xb = x + b * 96;

    // ---- stage 1: inputs + first weight set ----
    for (int idx = tid; idx < 96; idx += 128) sx[idx] = xb[idx];
    for (int idx = tid; idx < 160; idx += 128) {
        int m = idx / 5, k = idx % 5;
        sWe1[k * 32 + m] = We1[idx];
    }
    for (int idx = tid; idx < 2048; idx += 128) {        // Wu1 cols 32..95 -> R1[k*32+m]
        int k = idx >> 5, m = idx & 31;
        R1[idx] = Wu1[m * 96 + 32 + k];
    }
    for (int idx = tid; idx < 1024; idx += 128) {
        int r = idx >> 5, c = idx & 31;
        R2[c * 32 + r] = Wv2e[idx];                      // Wv2e[m][h] -> [h][m]
        R4[c * 32 + r] = Wu2[idx];                       // Wu2[m][k]  -> [k][m]
        R5[c * 32 + r] = We2v[idx];                      // We2v[h][m] -> [m][h]
    }
    if (tid < 32) { sbe1[tid] = be1[tid]; sbe2[tid] = be2[tid]; sbu2[tid] = bu2[tid]; }
    __syncthreads();

    // ---- h_v ----
    for (int idx = tid; idx < 1024; idx += 128) {
        int n = idx >> 5, h = idx & 31;
        float sf = (n >= 16) ? 1.f : 0.f;
        s_hv[idx] = b_node[h]
                  + sx[n*3+0] * W_node[h*4+0]
                  + sx[n*3+1] * W_node[h*4+1]
                  + sx[n*3+2] * W_node[h*4+2]
                  + sf        * W_node[h*4+3];
    }
    __syncthreads();

    // ---- p = h_v @ Wv2e^T ----
    for (int idx = tid; idx < 1024; idx += 128) {
        int n = idx >> 5, m = idx & 31;
        float acc = 0.f;
        #pragma unroll
        for (int h = 0; h < 32; h++) acc += s_hv[n*32 + h] * R2[h*32 + m];
        s_pm[idx] = acc;
    }
    __syncthreads();

    // ---- hoist: A[n][m] = Wu1[m,32:64]·p[n] + bu1[m], B[n][m] = Wu1[m,64:96]·p[n]
    //      stored in packed-pair layout: float index ((m>>1)*32+n)*2 + (m&1)
    for (int idx = tid; idx < 1024; idx += 128) {
        int n = idx >> 5, m = idx & 31;
        float a = 0.f, bb = 0.f;
        #pragma unroll
        for (int k = 0; k < 32; k++) {
            float pv = s_pm[n*32 + k];
            a  += R1[k*32 + m]        * pv;
            bb += R1[(32 + k)*32 + m] * pv;
        }
        int dst = ((m >> 1) * 32 + n) * 2 + (m & 1);
        R2[dst] = a + bu1[m];
        R3[dst] = bb;
    }
    __syncthreads();

    // ---- restage R1 = [We2T | Wu1aT] ----
    for (int idx = tid; idx < 1024; idx += 128) {
        int r = idx >> 5, c = idx & 31;
        R1[c * 32 + r]        = We2[idx];                // We2[m][k] -> [k][m]
        R1[1024 + c * 32 + r] = Wu1[r * 96 + c];         // Wu1[m][0:32] -> [k][m]
    }
    __syncthreads();

    // ---- edge loop: warp handles row i, lane = j ----
    const float* We2T  = R1;
    const float* Wu1aT = R1 + 1024;
    const unsigned long long* be1u = reinterpret_cast<const unsigned long long*>(sbe1);
    const unsigned long long* be2u = reinterpret_cast<const unsigned long long*>(sbe2);
    const unsigned long long* bu2u = reinterpret_cast<const unsigned long long*>(sbu2);
    const unsigned long long* Au   = reinterpret_cast<const unsigned long long*>(R2);
    const unsigned long long* Bu   = reinterpret_cast<const unsigned long long*>(R3);

    const float xj0 = sx[lane*3+0], xj1 = sx[lane*3+1], xj2 = sx[lane*3+2];
    float psacc = 0.f, s1acc = 0.f, cuspacc = 0.f;

    #pragma unroll 1
    for (int bi = 0; bi < 8; bi++) {
        const int i = bi * 4 + w;
        const float xi0 = sx[i*3+0], xi1 = sx[i*3+1], xi2 = sx[i*3+2];
        const float r0 = xi0 - xj0, r1 = xi1 - xj1, r2c = xi2 - xj2;
        const float rr = r0*r0 + r1*r1 + r2c*r2c;
        const float d  = sqrtf(rr + 1e-12f);

        unsigned long long acc[16];

        // t1 = silu(We1 @ [r, r1, r2] + be1)
        #pragma unroll
        for (int p = 0; p < 16; p++) acc[p] = be1u[p];
        mac_row(sWe1 + 0*32,  pk2(r0, r0),  acc);
        mac_row(sWe1 + 1*32,  pk2(r1, r1),  acc);
        mac_row(sWe1 + 2*32,  pk2(r2c, r2c), acc);
        mac_row(sWe1 + 3*32,  pk2(d, d),    acc);
        mac_row(sWe1 + 4*32,  pk2(rr, rr),  acc);
        float t1f[32];
        #pragma unroll
        for (int p = 0; p < 16; p++) {
            float a0, a1; upk2(acc[p], a0, a1);
            t1f[2*p] = silu_f(a0); t1f[2*p+1] = silu_f(a1);
        }

        // h_e = We2 @ t1 + be2
        #pragma unroll
        for (int p = 0; p < 16; p++) acc[p] = be2u[p];
        matvec32(We2T, t1f, acc);
        float hef[32];
        #pragma unroll
        for (int p = 0; p < 16; p++) upk2(acc[p], hef[2*p], hef[2*p+1]);

        // t2 = silu(Wu1[:,0:32] @ h_e + A[i] + B[j])    (bu1 folded into A)
        #pragma unroll
        for (int p = 0; p < 16; p++) acc[p] = f2add(Au[p*32 + i], Bu[p*32 + lane]);
        matvec32(Wu1aT, hef, acc);
        float t2f[32];
        #pragma unroll
        for (int p = 0; p < 16; p++) {
            float a0, a1; upk2(acc[p], a0, a1);
            t2f[2*p] = silu_f(a0); t2f[2*p+1] = silu_f(a1);
        }

        // h_e_new = Wu2 @ t2 + bu2   (stays packed in acc)
        #pragma unroll
        for (int p = 0; p < 16; p++) acc[p] = bu2u[p];
        matvec32(R4, t2f, acc);

        const bool upper = (lane > i);

        // pair channel sums: sum_{j>i} (h_e + h_e_new)
        {
            unsigned long long v[16];
            #pragma unroll
            for (int p = 0; p < 16; p++)
                v[p] = upper ? f2add(pk2(hef[2*p], hef[2*p+1]), acc[p]) : 0ull;
            psacc += tree_reduce(v, lane);
        }
        // message sum: S[m] = sum_{j != i} h_e_new[j][m], then m_v[i] = We2v @ S
        {
            unsigned long long v[16];
            #pragma unroll
            for (int p = 0; p < 16; p++) v[p] = (lane == i) ? 0ull : acc[p];
            float S = tree_reduce(v, lane);
            float mv = 0.f;
            #pragma unroll
            for (int m = 0; m < 32; m++) {
                float sm = __shfl_sync(FULLM, S, m);
                mv += R5[m*32 + lane] * sm;
            }
            s_pm[i*32 + lane] = mv;
        }

        if (upper) {
            s1acc += log1pf((rr + 1e-8f) * 25.f);
            float rc = sqrtf(rr + 1e-30f);
            float gamma = ((i < 16) == (lane < 16)) ? 0.25f : 0.5f;
            cuspacc += gamma * rc * expf(-rc);
        }
    }
    s_ps[w*32 + lane] = psacc;
    {   // scalar warp reductions
        #pragma unroll
        for (int off = 16; off > 0; off >>= 1) {
            s1acc  += __shfl_down_sync(FULLM, s1acc, off);
            cuspacc += __shfl_down_sync(FULLM, cuspacc, off);
        }
        if (lane == 0) { s_sc[w] = s1acc; s_sc[4 + w] = cuspacc; }
    }
    __syncthreads();

    // ---- phase C: node update MLP ----
    for (int idx = tid; idx < 2048; idx += 128) {        // Wn1 -> R1[k*32+h]
        int h = idx >> 6, k = idx & 63;
        R1[k*32 + h] = Wn1[idx];
    }
    for (int idx = tid; idx < 1024; idx += 128) {        // Wn2 -> R4[k*32+h]
        int h = idx >> 5, k = idx & 31;
        R4[k*32 + h] = Wn2[idx];
    }
    if (tid < 32) { sbe1[tid] = bn1[tid]; sbe2[tid] = bn2[tid]; }
    __syncthreads();

    for (int idx = tid; idx < 1024; idx += 128) {
        int n = idx >> 5, h = idx & 31;
        float acc = sbe1[h];
        #pragma unroll
        for (int k = 0; k < 32; k++) acc += R1[k*32 + h] * s_hv[n*32 + k];
        #pragma unroll
        for (int k = 0; k < 32; k++) acc += R1[(32 + k)*32 + h] * s_pm[n*32 + k];
        R2[idx] = silu_f(acc);
    }
    __syncthreads();
    for (int idx = tid; idx < 1024; idx += 128) {
        int n = idx >> 5, h = idx & 31;
        float acc = sbe2[h];
        #pragma unroll
        for (int k = 0; k < 32; k++) acc += R4[k*32 + h] * R2[n*32 + k];
        R3[idx] = s_hv[idx] + acc;                       // updated h_v
    }
    __syncthreads();

    // ---- assemble f_in (130) ----
    if (tid < 32) {
        float acc = 0.f;
        for (int n = 0; n < 32; n++) acc += R3[n*32 + tid];
        s_fin[tid]      = acc;
        s_fin[32 + tid] = acc * (1.f / 32.f);
        float ps = 0.f;
        for (int ww = 0; ww < 4; ww++) ps += s_ps[ww*32 + tid];
        s_fin[64 + tid] = ps;
        s_fin[96 + tid] = ps * (1.f / 496.f);
    }
    if (tid == 0) {
        float r2m = 0.f;
        for (int t = 0; t < 96; t++) r2m += sx[t] * sx[t];
        s_fin[128] = r2m * (1.f / 96.f);
        float s1 = 0.f, cu = 0.f;
        for (int ww = 0; ww < 4; ww++) { s1 += s_sc[ww]; cu += s_sc[4 + ww]; }
        s_fin[129] = s1 * (1.f / 496.f);
        s_sc[8] = cu;
    }
    __syncthreads();

    // ---- final MLP 130 -> 64 -> 64 -> 1 ----
    for (int o = w; o < 64; o += 4) {
        float acc = 0.f;
        for (int k = lane; k < 130; k += 32) acc += Wf1[o*130 + k] * s_fin[k];
        #pragma unroll
        for (int off = 16; off > 0; off >>= 1) acc += __shfl_down_sync(FULLM, acc, off);
        if (lane == 0) s_f1[o] = silu_f(acc + bf1[o]);
    }
    __syncthreads();
    for (int o = w; o < 64; o += 4) {
        float acc = Wf2[o*64 + lane] * s_f1[lane] + Wf2[o*64 + 32 + lane] * s_f1[32 + lane];
        #pragma unroll
        for (int off = 16; off > 0; off >>= 1) acc += __shfl_down_sync(FULLM, acc, off);
        if (lane == 0) s_f2[o] = silu_f(acc + bf2[o]);
    }
    __syncthreads();
    if (w == 0) {
        float acc = Wf3[lane] * s_f2[lane] + Wf3[32 + lane] * s_f2[32 + lane];
        #pragma unroll
        for (int off = 16; off > 0; off >>= 1) acc += __shfl_down_sync(FULLM, acc, off);
        if (lane == 0) out[b] = acc + bf3[0] + s_sc[8];
    }
}

extern "C" void kernel_launch(void* const* d_in, const int* in_sizes, int n_in,
                              void* d_out, int out_size) {
    const float* x      = (const float*)d_in[0];
    const float* W_node = (const float*)d_in[1];
    const float* b_node = (const float*)d_in[2];
    const float* We1    = (const float*)d_in[3];
    const float* be1    = (const float*)d_in[4];
    const float* We2    = (const float*)d_in[5];
    const float* be2    = (const float*)d_in[6];
    const float* Wv2e   = (const float*)d_in[7];
    const float* We2v   = (const float*)d_in[8];
    const float* Wu1    = (const float*)d_in[9];
    const float* bu1    = (const float*)d_in[10];
    const float* Wu2    = (const float*)d_in[11];
    const float* bu2    = (const float*)d_in[12];
    const float* Wn1    = (const float*)d_in[13];
    const float* bn1    = (const float*)d_in[14];
    const float* Wn2    = (const float*)d_in[15];
    const float* bn2    = (const float*)d_in[16];
    const float* Wf1    = (const float*)d_in[17];
    const float* bf1    = (const float*)d_in[18];
    const float* Wf2    = (const float*)d_in[19];
    const float* bf2    = (const float*)d_in[20];
    const float* Wf3    = (const float*)d_in[21];
    const float* bf3    = (const float*)d_in[22];

    int B = in_sizes[0] / 96;
    jastrow_kernel<<<B, 128>>>(x, W_node, b_node, We1, be1, We2, be2,
                               Wv2e, We2v, Wu1, bu1, Wu2, bu2,
                               Wn1, bn1, Wn2, bn2,
                               Wf1, bf1, Wf2, bf2, Wf3, bf3,
                               (float*)d_out);
}

// round 5
// speedup vs baseline: 4.0636x; 1.7882x over previous
#include <cuda_runtime.h>
#include <math.h>

#define FULLM 0xffffffffu
typedef unsigned long long ull;

__device__ __forceinline__ float silu_f(float v) {
    return __fdividef(v, 1.f + __expf(-v));
}

// ---- f32x2 packed helpers (Blackwell) ----
__device__ __forceinline__ ull pk2(float lo, float hi) {
    ull r; asm("mov.b64 %0,{%1,%2};" : "=l"(r) : "f"(lo), "f"(hi)); return r;
}
__device__ __forceinline__ void upk2(ull v, float& lo, float& hi) {
    asm("mov.b64 {%0,%1},%2;" : "=f"(lo), "=f"(hi) : "l"(v));
}
__device__ __forceinline__ ull f2fma(ull a, ull b, ull c) {
    ull r; asm("fma.rn.f32x2 %0,%1,%2,%3;" : "=l"(r) : "l"(a), "l"(b), "l"(c)); return r;
}
__device__ __forceinline__ ull f2add(ull a, ull b) {
    ull r; asm("add.rn.f32x2 %0,%1,%2;" : "=l"(r) : "l"(a), "l"(b)); return r;
}

// one weight row (32 ch packed as 8 ull2) times scalar-dup td — uniform LDS.128
__device__ __forceinline__ void mac_row(const float* __restrict__ Wrow, ull td, ull acc[16]) {
    const ulonglong2* r = reinterpret_cast<const ulonglong2*>(Wrow);
    #pragma unroll
    for (int q = 0; q < 8; q++) {
        ulonglong2 w = r[q];
        acc[2*q]   = f2fma(w.x, td, acc[2*q]);
        acc[2*q+1] = f2fma(w.y, td, acc[2*q+1]);
    }
}

__device__ __forceinline__ void matvec32(const float* __restrict__ W, const float* __restrict__ vin,
                                         ull acc[16]) {
    #pragma unroll
    for (int k = 0; k < 32; k++) mac_row(W + k * 32, pk2(vin[k], vin[k]), acc);
}

// column-sum of a (lane x 32ch) packed register matrix; returns channel==lane value
__device__ __forceinline__ float tree_reduce(const ull v[16], int lane) {
    ull a[8];
    const bool b4 = (lane & 16) != 0;
    #pragma unroll
    for (int q = 0; q < 8; q++) {
        ull send = b4 ? v[q] : v[q + 8];
        ull keep = b4 ? v[q + 8] : v[q];
        a[q] = f2add(keep, __shfl_xor_sync(FULLM, send, 16));
    }
    ull b[4];
    const bool b3 = (lane & 8) != 0;
    #pragma unroll
    for (int q = 0; q < 4; q++) {
        ull send = b3 ? a[q] : a[q + 4];
        ull keep = b3 ? a[q + 4] : a[q];
        b[q] = f2add(keep, __shfl_xor_sync(FULLM, send, 8));
    }
    ull c[2];
    const bool b2 = (lane & 4) != 0;
    #pragma unroll
    for (int q = 0; q < 2; q++) {
        ull send = b2 ? b[q] : b[q + 2];
        ull keep = b2 ? b[q + 2] : b[q];
        c[q] = f2add(keep, __shfl_xor_sync(FULLM, send, 4));
    }
    const bool b1 = (lane & 2) != 0;
    ull s1v = b1 ? c[0] : c[1];
    ull k1v = b1 ? c[1] : c[0];
    ull e = f2add(k1v, __shfl_xor_sync(FULLM, s1v, 2));
    float lo, hi;
    upk2(e, lo, hi);
    const bool b0 = (lane & 1) != 0;
    float snd = b0 ? lo : hi;
    float kp  = b0 ? hi : lo;
    return kp + __shfl_xor_sync(FULLM, snd, 1);
}

__global__ void __launch_bounds__(128, 4)
jastrow_kernel(
    const float* __restrict__ x,
    const float* __restrict__ W_node, const float* __restrict__ b_node,
    const float* __restrict__ We1,    const float* __restrict__ be1,
    const float* __restrict__ We2,    const float* __restrict__ be2,
    const float* __restrict__ Wv2e,   const float* __restrict__ We2v,
    const float* __restrict__ Wu1,    const float* __restrict__ bu1,
    const float* __restrict__ Wu2,    const float* __restrict__ bu2,
    const float* __restrict__ Wn1,    const float* __restrict__ bn1,
    const float* __restrict__ Wn2,    const float* __restrict__ bn2,
    const float* __restrict__ Wf1,    const float* __restrict__ bf1,
    const float* __restrict__ Wf2,    const float* __restrict__ bf2,
    const float* __restrict__ Wf3,    const float* __restrict__ bf3,
    float* __restrict__ out)
{
    // ~40.5 KB static shared, region-reused
    __shared__ __align__(16) float sWe1[160];
    __shared__ __align__(16) float sWcT[1024];   // p (temp) -> Wc^T -> Wn1T[0:32]
    __shared__ __align__(16) float sWe2T[1024];  // We2^T (kept for Wc + hesum)
    __shared__ __align__(16) float sWu2T[1024];  // Wu2^T (kept for Wd + hesum)
    __shared__ __align__(16) float sWdT[1024];   // Wv2e^T (temp) -> Wd^T
    __shared__ __align__(16) float sAp[1024];    // Wu1T[32:64] -> A packed -> Wn1T[32:64]
    __shared__ __align__(16) float sBp[1024];    // Wu1T[64:96] -> B packed -> Wn2T
    __shared__ __align__(16) float s_hv[1024];   // h_v, updated in place at the end
    __shared__ __align__(16) float s_pm[1024];   // Wu1aT -> S' -> u1
    __shared__ __align__(16) float s_mv[1024];   // We2vT -> m_v
    __shared__ __align__(16) float sbe1[32];
    __shared__ __align__(16) float s_cb[64];     // be2 | bu2
    __shared__ float s_mvc[32];
    __shared__ float sx[96];
    __shared__ float s_ps1[128], s_ps2[128];
    __shared__ float s_sc[12];
    __shared__ float s_fin[132];
    __shared__ float s_f1[64], s_f2[64];

    const int tid  = threadIdx.x;
    const int w    = tid >> 5;
    const int lane = tid & 31;
    const int b    = blockIdx.x;
    const float* xb = x + b * 96;

    // ---- S0: stage everything ----
    for (int idx = tid; idx < 96; idx += 128) sx[idx] = xb[idx];
    for (int idx = tid; idx < 160; idx += 128) {
        int m = idx / 5, k = idx % 5;
        sWe1[k * 32 + m] = We1[idx];
    }
    #pragma unroll
    for (int t = 0; t < 8; t++) {
        int idx = tid + t * 128;
        int r = idx >> 5, c = idx & 31;
        sWe2T[c*32 + r] = We2[idx];      // We2[r][c]  -> [k][m]
        sWu2T[c*32 + r] = Wu2[idx];      // Wu2[t][m] at sWu2T[m*32+t]
        sWdT [c*32 + r] = Wv2e[idx];     // Wv2e[m][h] at sWdT[h*32+m]  (temp)
        s_mv [c*32 + r] = We2v[idx];     // We2v[h][t] at s_mv[t*32+h]  (temp)
        s_pm [c*32 + r] = Wu1[r*96 + c]; // Wu1aT: Wu1[m][k] at s_pm[k*32+m]
    }
    for (int idx = tid; idx < 2048; idx += 128) {   // Wu1 cols 32..95
        int c = idx >> 5, m = idx & 31;
        float v = Wu1[m*96 + 32 + c];
        if (c < 32) sAp[c*32 + m] = v; else sBp[(c-32)*32 + m] = v;
    }
    if (tid < 32) { sbe1[tid] = be1[tid]; s_cb[tid] = be2[tid]; s_cb[32+tid] = bu2[tid]; }
    __syncthreads();

    // ---- h_v ----
    #pragma unroll
    for (int t = 0; t < 8; t++) {
        int idx = tid + t * 128;
        int n = idx >> 5, h = idx & 31;
        float sf = (n >= 16) ? 1.f : 0.f;
        s_hv[idx] = b_node[h]
                  + sx[n*3+0] * W_node[h*4+0]
                  + sx[n*3+1] * W_node[h*4+1]
                  + sx[n*3+2] * W_node[h*4+2]
                  + sf        * W_node[h*4+3];
    }
    __syncthreads();

    // ---- p = h_v @ Wv2e^T  (into sWcT as temp) ----
    #pragma unroll
    for (int t = 0; t < 8; t++) {
        int idx = tid + t * 128;
        int n = idx >> 5, m = idx & 31;
        float acc = 0.f;
        #pragma unroll
        for (int h = 0; h < 32; h++) acc += s_hv[n*32 + h] * sWdT[h*32 + m];
        sWcT[idx] = acc;
    }
    __syncthreads();

    // ---- S3: compute A/B, Wc, Wd, mvc into registers ----
    const int m0 = tid & 31, nb = tid >> 5;
    float dm = 0.f;                               // d[m] = Wu1a @ be2
    #pragma unroll
    for (int t2 = 0; t2 < 32; t2++) dm += s_pm[t2*32 + m0] * s_cb[t2];
    const float bu1m = bu1[m0];
    float av[8], bv[8];
    #pragma unroll
    for (int t = 0; t < 8; t++) {
        int n = nb + t * 4;
        float a = 0.f, bb = 0.f;
        #pragma unroll
        for (int k = 0; k < 32; k++) {
            float pv = sWcT[n*32 + k];
            a  += sAp[k*32 + m0] * pv;
            bb += sBp[k*32 + m0] * pv;
        }
        av[t] = a + bu1m + dm;
        bv[t] = bb;
    }
    float wc[8], wd[8];
    #pragma unroll
    for (int t = 0; t < 8; t++) {                 // WcT[k*32+m] = sum_t Wu1a[m][t] We2[t][k]
        int idx = tid + t * 128;
        int k = idx >> 5, mm = idx & 31;
        float s = 0.f;
        #pragma unroll
        for (int tt = 0; tt < 32; tt++) s += s_pm[tt*32 + mm] * sWe2T[k*32 + tt];
        wc[t] = s;
    }
    #pragma unroll
    for (int t = 0; t < 8; t++) {                 // WdT[m*32+h] = sum_t We2v[h][t] Wu2[t][m]
        int idx = tid + t * 128;
        int mm = idx >> 5, h = idx & 31;
        float s = 0.f;
        #pragma unroll
        for (int tt = 0; tt < 32; tt++) s += s_mv[tt*32 + h] * sWu2T[mm*32 + tt];
        wd[t] = s;
    }
    float mvcv = 0.f;
    if (tid < 32) {
        #pragma unroll
        for (int tt = 0; tt < 32; tt++) mvcv += s_mv[tt*32 + tid] * s_cb[32 + tt];
        mvcv *= 31.f;
    }
    __syncthreads();
    // ---- S4: commit ----
    #pragma unroll
    for (int t = 0; t < 8; t++) {
        int n = nb + t * 4;
        int dst = ((m0 >> 1) * 32 + n) * 2 + (m0 & 1);   // packed-pair layout
        sAp[dst] = av[t];
        sBp[dst] = bv[t];
    }
    #pragma unroll
    for (int t = 0; t < 8; t++) { int idx = tid + t * 128; sWcT[idx] = wc[t]; sWdT[idx] = wd[t]; }
    if (tid < 32) s_mvc[tid] = mvcv;
    __syncthreads();

    // ---- edge loop: warp = row i, lane = j.  Only t1 + one Wc matvec per edge ----
    const ull* be1u = reinterpret_cast<const ull*>(sbe1);
    const ull* Au   = reinterpret_cast<const ull*>(sAp);
    const ull* Bu   = reinterpret_cast<const ull*>(sBp);

    const float xj0 = sx[lane*3+0], xj1 = sx[lane*3+1], xj2 = sx[lane*3+2];
    float pst1acc = 0.f, pst2acc = 0.f, s1acc = 0.f, cuspacc = 0.f;

    #pragma unroll 1
    for (int bi = 0; bi < 8; bi++) {
        const int i = bi * 4 + w;
        const float xi0 = sx[i*3+0], xi1 = sx[i*3+1], xi2 = sx[i*3+2];
        const float r0 = xi0 - xj0, r1 = xi1 - xj1, r2c = xi2 - xj2;
        const float rr = r0*r0 + r1*r1 + r2c*r2c;
        const float d  = sqrtf(rr + 1e-12f);

        ull acc[16];
        #pragma unroll
        for (int p = 0; p < 16; p++) acc[p] = be1u[p];
        mac_row(sWe1 + 0*32,  pk2(r0, r0),   acc);
        mac_row(sWe1 + 1*32,  pk2(r1, r1),   acc);
        mac_row(sWe1 + 2*32,  pk2(r2c, r2c), acc);
        mac_row(sWe1 + 3*32,  pk2(d, d),     acc);
        mac_row(sWe1 + 4*32,  pk2(rr, rr),   acc);
        float t1f[32];
        #pragma unroll
        for (int p = 0; p < 16; p++) {
            float a0, a1; upk2(acc[p], a0, a1);
            t1f[2*p] = silu_f(a0); t1f[2*p+1] = silu_f(a1);
        }

        // t2 = silu(Wc@t1 + A[i] + B[j])   (A has bu1 + Wu1a@be2 folded in)
        #pragma unroll
        for (int p = 0; p < 16; p++) acc[p] = f2add(Au[p*32 + i], Bu[p*32 + lane]);
        matvec32(sWcT, t1f, acc);
        #pragma unroll
        for (int p = 0; p < 16; p++) {
            float a0, a1; upk2(acc[p], a0, a1);
            acc[p] = pk2(silu_f(a0), silu_f(a1));
        }

        const bool upper = (lane > i);

        {   // per-channel sum of t1 over unordered pairs
            ull v[16];
            #pragma unroll
            for (int p = 0; p < 16; p++) v[p] = upper ? pk2(t1f[2*p], t1f[2*p+1]) : 0ull;
            pst1acc += tree_reduce(v, lane);
        }
        {   // per-channel sum of t2 over unordered pairs
            ull v[16];
            #pragma unroll
            for (int p = 0; p < 16; p++) v[p] = upper ? acc[p] : 0ull;
            pst2acc += tree_reduce(v, lane);
        }
        {   // S'[i][ch] = sum_{j!=i} t2[j][ch]
            ull v[16];
            #pragma unroll
            for (int p = 0; p < 16; p++) v[p] = (lane == i) ? 0ull : acc[p];
            s_pm[i*32 + lane] = tree_reduce(v, lane);
        }

        if (upper) {
            s1acc += log1pf((rr + 1e-8f) * 25.f);
            float rc = sqrtf(rr + 1e-30f);
            float gamma = ((i < 16) == (lane < 16)) ? 0.25f : 0.5f;
            cuspacc += gamma * rc * expf(-rc);
        }
    }
    s_ps1[w*32 + lane] = pst1acc;
    s_ps2[w*32 + lane] = pst2acc;
    #pragma unroll
    for (int off = 16; off > 0; off >>= 1) {
        s1acc   += __shfl_down_sync(FULLM, s1acc, off);
        cuspacc += __shfl_down_sync(FULLM, cuspacc, off);
    }
    if (lane == 0) { s_sc[w] = s1acc; s_sc[4 + w] = cuspacc; }
    __syncthreads();

    // ---- post: m_v = Wd@S' + mvc ; Wn staging ; hesum ----
    #pragma unroll
    for (int t = 0; t < 8; t++) {
        int idx = tid + t * 128;
        int n = idx >> 5, h = idx & 31;
        float s = s_mvc[h];
        #pragma unroll
        for (int mm = 0; mm < 32; mm++) s += sWdT[mm*32 + h] * s_pm[n*32 + mm];
        s_mv[idx] = s;
    }
    for (int idx = tid; idx < 2048; idx += 128) {   // Wn1T split across sWcT | sAp
        int h = idx >> 6, k = idx & 63;
        float v = Wn1[idx];
        if (k < 32) sWcT[k*32 + h] = v; else sAp[(k-32)*32 + h] = v;
    }
    #pragma unroll
    for (int t = 0; t < 8; t++) {                   // Wn2T -> sBp
        int idx = tid + t * 128;
        int h = idx >> 5, k = idx & 31;
        sBp[k*32 + h] = Wn2[idx];
    }
    if (tid < 32) {                                  // pair-channel sums of (h_e + h_e_new)
        int ch = tid;
        float hs = 496.f * (s_cb[ch] + s_cb[32 + ch]);
        #pragma unroll
        for (int k = 0; k < 32; k++) {
            float p1 = s_ps1[k] + s_ps1[32+k] + s_ps1[64+k] + s_ps1[96+k];
            float p2 = s_ps2[k] + s_ps2[32+k] + s_ps2[64+k] + s_ps2[96+k];
            hs += sWe2T[k*32 + ch] * p1 + sWu2T[k*32 + ch] * p2;
        }
        s_fin[64 + ch] = hs;
        s_fin[96 + ch] = hs * (1.f / 496.f);
    }
    if (tid == 0) {
        float r2m = 0.f;
        for (int t = 0; t < 96; t++) r2m += sx[t] * sx[t];
        s_fin[128] = r2m * (1.f / 96.f);
        float s1 = 0.f, cu = 0.f;
        for (int ww = 0; ww < 4; ww++) { s1 += s_sc[ww]; cu += s_sc[4 + ww]; }
        s_fin[129] = s1 * (1.f / 496.f);
        s_sc[8] = cu;
    }
    __syncthreads();

    // ---- node MLP: u1 = silu(Wn1@[h_v; m_v] + bn1) ----
    #pragma unroll
    for (int t = 0; t < 8; t++) {
        int idx = tid + t * 128;
        int n = idx >> 5, h = idx & 31;
        float acc = bn1[h];
        #pragma unroll
        for (int k = 0; k < 32; k++) acc += sWcT[k*32 + h] * s_hv[n*32 + k];
        #pragma unroll
        for (int k = 0; k < 32; k++) acc += sAp[k*32 + h] * s_mv[n*32 + k];
        s_pm[idx] = silu_f(acc);
    }
    __syncthreads();
    #pragma unroll
    for (int t = 0; t < 8; t++) {                    // h_v += Wn2@u1 + bn2 (in place)
        int idx = tid + t * 128;
        int n = idx >> 5, h = idx & 31;
        float acc = bn2[h];
        #pragma unroll
        for (int k = 0; k < 32; k++) acc += sBp[k*32 + h] * s_pm[n*32 + k];
        s_hv[idx] += acc;
    }
    __syncthreads();

    // ---- f_in[0..63] ----
    if (tid < 32) {
        float acc = 0.f;
        for (int n = 0; n < 32; n++) acc += s_hv[n*32 + tid];
        s_fin[tid]      = acc;
        s_fin[32 + tid] = acc * (1.f / 32.f);
    }
    __syncthreads();

    // ---- final MLP 130 -> 64 -> 64 -> 1 ----
    for (int o = w; o < 64; o += 4) {
        float acc = 0.f;
        for (int k = lane; k < 130; k += 32) acc += Wf1[o*130 + k] * s_fin[k];
        #pragma unroll
        for (int off = 16; off > 0; off >>= 1) acc += __shfl_down_sync(FULLM, acc, off);
        if (lane == 0) s_f1[o] = silu_f(acc + bf1[o]);
    }
    __syncthreads();
    for (int o = w; o < 64; o += 4) {
        float acc = Wf2[o*64 + lane] * s_f1[lane] + Wf2[o*64 + 32 + lane] * s_f1[32 + lane];
        #pragma unroll
        for (int off = 16; off > 0; off >>= 1) acc += __shfl_down_sync(FULLM, acc, off);
        if (lane == 0) s_f2[o] = silu_f(acc + bf2[o]);
    }
    __syncthreads();
    if (w == 0) {
        float acc = Wf3[lane] * s_f2[lane] + Wf3[32 + lane] * s_f2[32 + lane];
        #pragma unroll
        for (int off = 16; off > 0; off >>= 1) acc += __shfl_down_sync(FULLM, acc, off);
        if (lane == 0) out[b] = acc + bf3[0] + s_sc[8];
    }
}

extern "C" void kernel_launch(void* const* d_in, const int* in_sizes, int n_in,
                              void* d_out, int out_size) {
    const float* x      = (const float*)d_in[0];
    const float* W_node = (const float*)d_in[1];
    const float* b_node = (const float*)d_in[2];
    const float* We1    = (const float*)d_in[3];
    const float* be1    = (const float*)d_in[4];
    const float* We2    = (const float*)d_in[5];
    const float* be2    = (const float*)d_in[6];
    const float* Wv2e   = (const float*)d_in[7];
    const float* We2v   = (const float*)d_in[8];
    const float* Wu1    = (const float*)d_in[9];
    const float* bu1    = (const float*)d_in[10];
    const float* Wu2    = (const float*)d_in[11];
    const float* bu2    = (const float*)d_in[12];
    const float* Wn1    = (const float*)d_in[13];
    const float* bn1    = (const float*)d_in[14];
    const float* Wn2    = (const float*)d_in[15];
    const float* bn2    = (const float*)d_in[16];
    const float* Wf1    = (const float*)d_in[17];
    const float* bf1    = (const float*)d_in[18];
    const float* Wf2    = (const float*)d_in[19];
    const float* bf2    = (const float*)d_in[20];
    const float* Wf3    = (const float*)d_in[21];
    const float* bf3    = (const float*)d_in[22];

    int B = in_sizes[0] / 96;
    jastrow_kernel<<<B, 128>>>(x, W_node, b_node, We1, be1, We2, be2,
                               Wv2e, We2v, Wu1, bu1, Wu2, bu2,
                               Wn1, bn1, Wn2, bn2,
                               Wf1, bf1, Wf2, bf2, Wf3, bf3,
                               (float*)d_out);
}